// round 10
// baseline (speedup 1.0000x reference)
#include <cuda_runtime.h>
#include <cstdint>

// Problem constants (fixed by the reference).
static constexpr int NU    = 100000;   // users
static constexpr int NI    = 50000;    // items
static constexpr int D     = 64;       // dim
static constexpr int NP    = 3;        // meta-paths
static constexpr int DEG   = 16;
static constexpr int EU    = NU * DEG; // edges per user path (1.6M)
static constexpr int EI    = NI * DEG; // edges per item path (0.8M)
static constexpr int BATCH = 8192;

static constexpr int MAXROWS  = 3 * BATCH;            // 24576 distinct flagged rows max
static constexpr int MAXSLOTS = MAXROWS * NP;         // 73728 (id, path) slots
static constexpr int BMW      = (NU + NI + 31) / 32;  // 4688 bitmap words (18.75 KB)
static constexpr int AGG4     = MAXSLOTS * D / 4;     // 1179648 float4s

// Scratch (static device memory; ~20 MB total).
__device__ float    g_agg[(size_t)MAXSLOTS * D];      // 18.9 MB compact, L2-resident
__device__ int      g_rowid[NU + NI];                 // 600 KB (-1 = not live)
__device__ unsigned g_bitmap[BMW];                    // 18.75 KB live-row bits
__device__ int      g_nlive;

static inline unsigned cdiv(long long a, long long b) { return (unsigned)((a + b - 1) / b); }

// ---------------------------------------------------------------------------
// K0: zero compact agg + clear rowid map, bitmap, live counter
// ---------------------------------------------------------------------------
__global__ void __launch_bounds__(256) k_clear() {
    int t = blockIdx.x * blockDim.x + threadIdx.x;
    if (t < AGG4) {
        reinterpret_cast<float4*>(g_agg)[t] = make_float4(0.f, 0.f, 0.f, 0.f);
    } else {
        int u = t - AGG4;
        if (u < NU + NI) g_rowid[u] = -1;
        else {
            int b = u - (NU + NI);
            if (b < BMW) g_bitmap[b] = 0u;
            else if (b == BMW) g_nlive = 0;
        }
    }
}

// ---------------------------------------------------------------------------
// K1: flag rows: set bitmap bit + CAS-claim compact id
// ---------------------------------------------------------------------------
__global__ void __launch_bounds__(256) k_flags(const int* __restrict__ ui,
                                               const int* __restrict__ ii,
                                               const int* __restrict__ ni) {
    int t = blockIdx.x * blockDim.x + threadIdx.x;
    int rg;
    if (t < BATCH)          rg = ui[t];
    else if (t < 2 * BATCH) rg = NU + ii[t - BATCH];
    else if (t < 3 * BATCH) rg = NU + ni[t - 2 * BATCH];
    else return;

    atomicOr(&g_bitmap[rg >> 5], 1u << (rg & 31));
    if (atomicCAS(&g_rowid[rg], -1, -2) == -1) {
        int id = atomicAdd(&g_nlive, 1);
        g_rowid[rg] = id;
    }
}

// ---------------------------------------------------------------------------
// K2: fused filter + scatter.  Each block caches the 18.75 KB live-row bitmap
//     in smem.  Warps take 32-edge groups grid-stride:
//       Phase A: lane-per-edge coalesced row load, LDS bitmap test; survivors
//                load rowid (L2 gather) + col + val (predicated).
//       Phase B: ballot; 2 survivors per step via half-warps, each 16 lanes x
//                (LDG.128 table gather -> red.global.add.v4.f32 into the
//                 compact, L2-resident accumulator).
// ---------------------------------------------------------------------------
__global__ void __launch_bounds__(256) k_scatter(const int*   __restrict__ u_rows,
                                                 const int*   __restrict__ u_cols,
                                                 const float* __restrict__ u_vals,
                                                 const int*   __restrict__ i_rows,
                                                 const int*   __restrict__ i_cols,
                                                 const float* __restrict__ i_vals,
                                                 const float* __restrict__ u_table,
                                                 const float* __restrict__ i_table) {
    __shared__ unsigned sbm[BMW];                // 18752 B
    for (int i = threadIdx.x; i < BMW; i += blockDim.x) sbm[i] = g_bitmap[i];
    __syncthreads();

    const int lane = threadIdx.x & 31;
    const int sub  = lane & 15;                  // position within half-warp
    const int half = lane >> 4;
    constexpr int NGRP = NP * (EU + EI) / 32;    // 225000 groups of 32 edges
    int gw = (blockIdx.x * blockDim.x + threadIdx.x) >> 5;
    int wstride = (gridDim.x * blockDim.x) >> 5;

    for (int grp = gw; grp < NGRP; grp += wstride) {
        int e0 = grp * 32;
        const int* rows; const int* cols; const float* vals; const float* table;
        int e, p, roff;
        if (e0 < NP * EU) {
            e = e0;            p = e / EU;
            rows = u_rows; cols = u_cols; vals = u_vals; table = u_table; roff = 0;
        } else {
            e = e0 - NP * EU;  p = e / EI;
            rows = i_rows; cols = i_cols; vals = i_vals; table = i_table; roff = NU;
        }

        int r = __ldg(rows + e + lane);
        int x = roff + r;
        bool ok = (sbm[x >> 5] >> (x & 31)) & 1u;
        int slot = 0, c = 0; float v = 0.f;
        if (ok) {
            slot = g_rowid[x] * NP + p;          // L2 gather, survivors only
            c = __ldg(cols + e + lane);
            v = __ldg(vals + e + lane);
        }

        unsigned m = __ballot_sync(0xffffffffu, ok);
        while (m) {
            int srcA = __ffs(m) - 1; m &= m - 1;
            int srcB = m ? (__ffs(m) - 1) : -1;
            if (srcB >= 0) m &= m - 1;
            int src = half ? srcB : srcA;
            bool act = (src >= 0);
            int sx = act ? src : 0;
            int   sl = __shfl_sync(0xffffffffu, slot, sx);
            int   cc = __shfl_sync(0xffffffffu, c,    sx);
            float vv = __shfl_sync(0xffffffffu, v,    sx);
            if (act) {
                float4 s = __ldg(reinterpret_cast<const float4*>(table + (size_t)cc * D) + sub);
                float* dst = g_agg + (size_t)sl * D + (size_t)sub * 4;
                asm volatile("red.global.add.v4.f32 [%0], {%1, %2, %3, %4};"
                             :: "l"(dst), "f"(s.x * vv), "f"(s.y * vv),
                                "f"(s.z * vv), "f"(s.w * vv)
                             : "memory");
            }
        }
    }
}

// ---------------------------------------------------------------------------
// K3: epilogue (proven round-8 shape).  float2-packed W in smem:
//     each matvec step = SHFL + LDS.64 + 2xFFMA.  All 6 arow loads prefetched.
// ---------------------------------------------------------------------------
__global__ void __launch_bounds__(256) k_out(const float* __restrict__ Wu,
                                             const float* __restrict__ Wi,
                                             const float* __restrict__ wb1,
                                             const float* __restrict__ wb2,
                                             const int*   __restrict__ ui,
                                             const int*   __restrict__ ii,
                                             const int*   __restrict__ ni,
                                             float*       __restrict__ out) {
    __shared__ float2 Ws2[NP * D * 32];          // 48 KB exactly

    constexpr int ROWS_PER_BLOCK = 128;          // 8 warps x 16 rows
    constexpr int BLK_PER_SEG = BATCH / ROWS_PER_BLOCK;  // 64
    int seg = blockIdx.x / BLK_PER_SEG;
    int blk = blockIdx.x % BLK_PER_SEG;

    const float* W    = (seg == 0) ? Wu  : Wi;
    const float* wbp  = (seg == 0) ? wb1 : wb2;
    const int*   idxA = (seg == 0) ? ui : ((seg == 1) ? ii : ni);
    const int    roff = (seg == 0) ? 0 : NU;

    // Pack W: Ws2[p*2048 + d*32 + c] = (W[p][d][c], W[p][d][c+32])
    for (int j = threadIdx.x; j < NP * D * 32; j += blockDim.x) {
        int p = j >> 11, rem = j & 2047, d = rem >> 5, c = rem & 31;
        const float* src = W + p * D * D + d * D + c;
        Ws2[j] = make_float2(__ldg(src), __ldg(src + 32));
    }
    float w0 = __ldg(wbp + 0), w1 = __ldg(wbp + 1), w2 = __ldg(wbp + 2);
    __syncthreads();

    int warp = threadIdx.x >> 5;
    int lane = threadIdx.x & 31;

    for (int i = 0; i < 16; i++) {
        int b = blk * ROWS_PER_BLOCK + warp * 16 + i;
        int idx = __ldg(idxA + b);
        int id = g_rowid[roff + idx];            // compact id (always >= 0)
        const float* base = g_agg + (size_t)(id * NP) * D;

        float aL[NP], aH[NP];
        #pragma unroll
        for (int p = 0; p < NP; p++) {
            aL[p] = base[p * D + lane];
            aH[p] = base[p * D + lane + 32];
        }

        float accL = 0.f, accH = 0.f;
        #pragma unroll
        for (int p = 0; p < NP; p++) {
            float mL = 0.f, mH = 0.f;
            const float2* Wp = Ws2 + p * 2048;
            #pragma unroll
            for (int d = 0; d < 32; d++) {
                float ad = __shfl_sync(0xffffffffu, aL[p], d);
                float2 w = Wp[d * 32 + lane];
                mL += ad * w.x;
                mH += ad * w.y;
            }
            #pragma unroll
            for (int d = 0; d < 32; d++) {
                float ad = __shfl_sync(0xffffffffu, aH[p], d);
                float2 w = Wp[(d + 32) * 32 + lane];
                mL += ad * w.x;
                mH += ad * w.y;
            }
            float wp = (p == 0) ? w0 : ((p == 1) ? w1 : w2);
            accL += wp * fmaxf(mL, 0.f);
            accH += wp * fmaxf(mH, 0.f);
        }
        float* o = out + ((size_t)seg * BATCH + b) * D;
        o[lane]      = fmaxf(accL, 0.f);
        o[lane + 32] = fmaxf(accH, 0.f);
    }
}

// ---------------------------------------------------------------------------
// Launch
// ---------------------------------------------------------------------------
extern "C" void kernel_launch(void* const* d_in, const int* in_sizes, int n_in,
                              void* d_out, int out_size) {
    const float* user_table = (const float*)d_in[0];
    const float* item_table = (const float*)d_in[1];
    const float* Wu         = (const float*)d_in[2];
    const float* Wi         = (const float*)d_in[3];
    const float* wb1        = (const float*)d_in[4];
    const float* wb2        = (const float*)d_in[5];
    const float* user_vals  = (const float*)d_in[6];
    const float* item_vals  = (const float*)d_in[7];
    const int*   user_rows  = (const int*)d_in[8];
    const int*   user_cols  = (const int*)d_in[9];
    const int*   item_rows  = (const int*)d_in[10];
    const int*   item_cols  = (const int*)d_in[11];
    const int*   user_idx   = (const int*)d_in[12];
    const int*   item_idx   = (const int*)d_in[13];
    const int*   neg_idx    = (const int*)d_in[14];
    float* out = (float*)d_out;

    k_clear<<<cdiv(AGG4 + NU + NI + BMW + 1, 256), 256>>>();
    k_flags<<<cdiv(3 * BATCH, 256), 256>>>(user_idx, item_idx, neg_idx);
    k_scatter<<<1184, 256>>>(user_rows, user_cols, user_vals,
                             item_rows, item_cols, item_vals,
                             user_table, item_table);
    k_out<<<3 * (BATCH / 128), 256>>>(Wu, Wi, wb1, wb2, user_idx, item_idx, neg_idx, out);
}

// round 11
// speedup vs baseline: 1.4125x; 1.4125x over previous
#include <cuda_runtime.h>
#include <cstdint>

// Problem constants (fixed by the reference).
static constexpr int NU    = 100000;   // users
static constexpr int NI    = 50000;    // items
static constexpr int D     = 64;       // dim
static constexpr int NP    = 3;        // meta-paths
static constexpr int DEG   = 16;
static constexpr int EU    = NU * DEG; // edges per user path (1.6M)
static constexpr int EI    = NI * DEG; // edges per item path (0.8M)
static constexpr int BATCH = 8192;

static constexpr int MAXROWS  = 3 * BATCH;            // 24576 distinct flagged rows max
static constexpr int MAXSLOTS = MAXROWS * NP;         // 73728 (id, path) slots
static constexpr int BMW      = (NU + NI + 31) / 32;  // 4688 bitmap words (18.75 KB)
static constexpr int AGG4     = MAXSLOTS * D / 4;     // 1179648 float4s

// Scratch (static device memory; ~20 MB total).
__device__ float    g_agg[(size_t)MAXSLOTS * D];      // 18.9 MB compact, L2-resident
__device__ int      g_rowid[NU + NI];                 // 600 KB (-1 = not live)
__device__ unsigned g_bitmap[BMW];                    // 18.75 KB live-row bits
__device__ int      g_nlive;

static inline unsigned cdiv(long long a, long long b) { return (unsigned)((a + b - 1) / b); }

// ---------------------------------------------------------------------------
// K0: zero compact agg + clear rowid map, bitmap, live counter
// ---------------------------------------------------------------------------
__global__ void __launch_bounds__(256) k_clear() {
    int t = blockIdx.x * blockDim.x + threadIdx.x;
    if (t < AGG4) {
        reinterpret_cast<float4*>(g_agg)[t] = make_float4(0.f, 0.f, 0.f, 0.f);
    } else {
        int u = t - AGG4;
        if (u < NU + NI) g_rowid[u] = -1;
        else {
            int b = u - (NU + NI);
            if (b < BMW) g_bitmap[b] = 0u;
            else if (b == BMW) g_nlive = 0;
        }
    }
}

// ---------------------------------------------------------------------------
// K1: flag rows: set bitmap bit + CAS-claim compact id
// ---------------------------------------------------------------------------
__global__ void __launch_bounds__(256) k_flags(const int* __restrict__ ui,
                                               const int* __restrict__ ii,
                                               const int* __restrict__ ni) {
    int t = blockIdx.x * blockDim.x + threadIdx.x;
    int rg;
    if (t < BATCH)          rg = ui[t];
    else if (t < 2 * BATCH) rg = NU + ii[t - BATCH];
    else if (t < 3 * BATCH) rg = NU + ni[t - 2 * BATCH];
    else return;

    atomicOr(&g_bitmap[rg >> 5], 1u << (rg & 31));
    if (atomicCAS(&g_rowid[rg], -1, -2) == -1) {
        int id = atomicAdd(&g_nlive, 1);
        g_rowid[rg] = id;
    }
}

// ---------------------------------------------------------------------------
// K2: fused filter + scatter (proven round-10 shape).  SMEM bitmap filter,
//     ballot/half-warp cooperative red.v4 scatter into L2-resident agg.
// ---------------------------------------------------------------------------
__global__ void __launch_bounds__(256) k_scatter(const int*   __restrict__ u_rows,
                                                 const int*   __restrict__ u_cols,
                                                 const float* __restrict__ u_vals,
                                                 const int*   __restrict__ i_rows,
                                                 const int*   __restrict__ i_cols,
                                                 const float* __restrict__ i_vals,
                                                 const float* __restrict__ u_table,
                                                 const float* __restrict__ i_table) {
    __shared__ unsigned sbm[BMW];                // 18752 B
    for (int i = threadIdx.x; i < BMW; i += blockDim.x) sbm[i] = g_bitmap[i];
    __syncthreads();

    const int lane = threadIdx.x & 31;
    const int sub  = lane & 15;
    const int half = lane >> 4;
    constexpr int NGRP = NP * (EU + EI) / 32;    // 225000 groups of 32 edges
    int gw = (blockIdx.x * blockDim.x + threadIdx.x) >> 5;
    int wstride = (gridDim.x * blockDim.x) >> 5;

    for (int grp = gw; grp < NGRP; grp += wstride) {
        int e0 = grp * 32;
        const int* rows; const int* cols; const float* vals; const float* table;
        int e, p, roff;
        if (e0 < NP * EU) {
            e = e0;            p = e / EU;
            rows = u_rows; cols = u_cols; vals = u_vals; table = u_table; roff = 0;
        } else {
            e = e0 - NP * EU;  p = e / EI;
            rows = i_rows; cols = i_cols; vals = i_vals; table = i_table; roff = NU;
        }

        int r = __ldg(rows + e + lane);
        int x = roff + r;
        bool ok = (sbm[x >> 5] >> (x & 31)) & 1u;
        int slot = 0, c = 0; float v = 0.f;
        if (ok) {
            slot = g_rowid[x] * NP + p;
            c = __ldg(cols + e + lane);
            v = __ldg(vals + e + lane);
        }

        unsigned m = __ballot_sync(0xffffffffu, ok);
        while (m) {
            int srcA = __ffs(m) - 1; m &= m - 1;
            int srcB = m ? (__ffs(m) - 1) : -1;
            if (srcB >= 0) m &= m - 1;
            int src = half ? srcB : srcA;
            bool act = (src >= 0);
            int sx = act ? src : 0;
            int   sl = __shfl_sync(0xffffffffu, slot, sx);
            int   cc = __shfl_sync(0xffffffffu, c,    sx);
            float vv = __shfl_sync(0xffffffffu, v,    sx);
            if (act) {
                float4 s = __ldg(reinterpret_cast<const float4*>(table + (size_t)cc * D) + sub);
                float* dst = g_agg + (size_t)sl * D + (size_t)sub * 4;
                asm volatile("red.global.add.v4.f32 [%0], {%1, %2, %3, %4};"
                             :: "l"(dst), "f"(s.x * vv), "f"(s.y * vv),
                                "f"(s.z * vv), "f"(s.w * vv)
                             : "memory");
            }
        }
    }
}

// ---------------------------------------------------------------------------
// K3: epilogue as register-tiled SGEMM.
//     Block = 64 rows x 64 cols; per path: stage W_p (k-major) and gathered A
//     rows TRANSPOSED in smem; 256 threads each compute a 4x4 micro-tile:
//     per k-step 2 x LDS.128 + 16 independent FFMA.
//     acc += wb_p * relu(m_p); out = relu(acc).
// ---------------------------------------------------------------------------
static constexpr int TROWS = 64;                 // rows per block
static constexpr int SPAD  = 68;                 // padded row stride (16B-aligned)

__global__ void __launch_bounds__(256) k_out(const float* __restrict__ Wu,
                                             const float* __restrict__ Wi,
                                             const float* __restrict__ wb1,
                                             const float* __restrict__ wb2,
                                             const int*   __restrict__ ui,
                                             const int*   __restrict__ ii,
                                             const int*   __restrict__ ni,
                                             float*       __restrict__ out) {
    __shared__ float As[D * SPAD];               // As[k*SPAD + r], 17.4 KB
    __shared__ float Ws[D * SPAD];               // Ws[k*SPAD + c], 17.4 KB
    __shared__ int   sid[TROWS];

    constexpr int BLK_PER_SEG = BATCH / TROWS;   // 128
    int seg = blockIdx.x / BLK_PER_SEG;
    int blk = blockIdx.x % BLK_PER_SEG;

    const float* W    = (seg == 0) ? Wu  : Wi;
    const float* wbp  = (seg == 0) ? wb1 : wb2;
    const int*   idxA = (seg == 0) ? ui : ((seg == 1) ? ii : ni);
    const int    roff = (seg == 0) ? 0 : NU;

    int tid = threadIdx.x;
    if (tid < TROWS) {
        int idx = __ldg(idxA + blk * TROWS + tid);
        sid[tid] = g_rowid[roff + idx];          // compact id, >= 0
    }
    float w0 = __ldg(wbp + 0), w1 = __ldg(wbp + 1), w2 = __ldg(wbp + 2);
    __syncthreads();

    int tx = tid & 15;                           // col group: c0 = tx*4
    int ty = tid >> 4;                           // row group: r0 = ty*4
    int c0 = tx * 4, r0 = ty * 4;

    float acc[4][4];
    #pragma unroll
    for (int i = 0; i < 4; i++)
        #pragma unroll
        for (int j = 0; j < 4; j++) acc[i][j] = 0.f;

    for (int p = 0; p < NP; p++) {
        // Stage W_p: Ws[k][c] = W[p][k][c]  (coalesced 64-float rows)
        #pragma unroll
        for (int j = tid; j < D * D; j += 256) {
            int k = j >> 6, c = j & 63;
            Ws[k * SPAD + c] = __ldg(W + p * D * D + j);
        }
        // Stage A transposed: As[k][r] = g_agg[(sid[r]*NP+p)*64 + k]
        // groups of 64 threads read one agg row coalesced (256 B)
        #pragma unroll
        for (int j = tid; j < TROWS * D; j += 256) {
            int r = j >> 6, k = j & 63;
            As[k * SPAD + r] = g_agg[(size_t)(sid[r] * NP + p) * D + k];
        }
        __syncthreads();

        float m[4][4];
        #pragma unroll
        for (int i = 0; i < 4; i++)
            #pragma unroll
            for (int j = 0; j < 4; j++) m[i][j] = 0.f;

        #pragma unroll
        for (int k = 0; k < D; k++) {
            float4 a = *reinterpret_cast<const float4*>(&As[k * SPAD + r0]);
            float4 b = *reinterpret_cast<const float4*>(&Ws[k * SPAD + c0]);
            float av[4] = {a.x, a.y, a.z, a.w};
            float bv[4] = {b.x, b.y, b.z, b.w};
            #pragma unroll
            for (int i = 0; i < 4; i++)
                #pragma unroll
                for (int j = 0; j < 4; j++)
                    m[i][j] += av[i] * bv[j];
        }

        float wp = (p == 0) ? w0 : ((p == 1) ? w1 : w2);
        #pragma unroll
        for (int i = 0; i < 4; i++)
            #pragma unroll
            for (int j = 0; j < 4; j++)
                acc[i][j] += wp * fmaxf(m[i][j], 0.f);
        __syncthreads();                         // before next path overwrites smem
    }

    // Write 4x4 tile with final relu (float4 rows)
    #pragma unroll
    for (int i = 0; i < 4; i++) {
        float4 o4 = make_float4(fmaxf(acc[i][0], 0.f), fmaxf(acc[i][1], 0.f),
                                fmaxf(acc[i][2], 0.f), fmaxf(acc[i][3], 0.f));
        float* o = out + ((size_t)seg * BATCH + blk * TROWS + r0 + i) * D + c0;
        *reinterpret_cast<float4*>(o) = o4;
    }
}

// ---------------------------------------------------------------------------
// Launch
// ---------------------------------------------------------------------------
extern "C" void kernel_launch(void* const* d_in, const int* in_sizes, int n_in,
                              void* d_out, int out_size) {
    const float* user_table = (const float*)d_in[0];
    const float* item_table = (const float*)d_in[1];
    const float* Wu         = (const float*)d_in[2];
    const float* Wi         = (const float*)d_in[3];
    const float* wb1        = (const float*)d_in[4];
    const float* wb2        = (const float*)d_in[5];
    const float* user_vals  = (const float*)d_in[6];
    const float* item_vals  = (const float*)d_in[7];
    const int*   user_rows  = (const int*)d_in[8];
    const int*   user_cols  = (const int*)d_in[9];
    const int*   item_rows  = (const int*)d_in[10];
    const int*   item_cols  = (const int*)d_in[11];
    const int*   user_idx   = (const int*)d_in[12];
    const int*   item_idx   = (const int*)d_in[13];
    const int*   neg_idx    = (const int*)d_in[14];
    float* out = (float*)d_out;

    k_clear<<<cdiv(AGG4 + NU + NI + BMW + 1, 256), 256>>>();
    k_flags<<<cdiv(3 * BATCH, 256), 256>>>(user_idx, item_idx, neg_idx);
    k_scatter<<<1184, 256>>>(user_rows, user_cols, user_vals,
                             item_rows, item_cols, item_vals,
                             user_table, item_table);
    k_out<<<3 * (BATCH / TROWS), 256>>>(Wu, Wi, wb1, wb2, user_idx, item_idx, neg_idx, out);
}

// round 12
// speedup vs baseline: 1.5590x; 1.1037x over previous
#include <cuda_runtime.h>
#include <cstdint>

// Problem constants (fixed by the reference).
static constexpr int NU    = 100000;   // users
static constexpr int NI    = 50000;    // items
static constexpr int D     = 64;       // dim
static constexpr int NP    = 3;        // meta-paths
static constexpr int DEG   = 16;
static constexpr int EU    = NU * DEG; // edges per user path (1.6M)
static constexpr int EI    = NI * DEG; // edges per item path (0.8M)
static constexpr int BATCH = 8192;

static constexpr int UIDS     = BATCH;                // user id region [0, 8192)
static constexpr int MAXROWS  = 3 * BATCH;            // 24576 ids total (items at [8192, 24576))
static constexpr int MAXSLOTS = MAXROWS * NP;         // 73728 (id, path) slots
static constexpr int BMW      = (NU + NI + 31) / 32;  // 4688 bitmap words (18.75 KB)
static constexpr int AGG4     = MAXSLOTS * D / 4;     // 1179648 float4s

// Scratch (static device memory; ~39 MB total).
__device__ float    g_agg[(size_t)MAXSLOTS * D];      // 18.9 MB  pre-W aggregation
__device__ float    g_m[(size_t)MAXSLOTS * D];        // 18.9 MB  per-path GEMM result
__device__ int      g_rowid[NU + NI];                 // 600 KB (-1 = not live)
__device__ unsigned g_bitmap[BMW];                    // 18.75 KB live-row bits
__device__ int      g_nlive_u;
__device__ int      g_nlive_i;

static inline unsigned cdiv(long long a, long long b) { return (unsigned)((a + b - 1) / b); }

// ---------------------------------------------------------------------------
// K0: zero agg + clear rowid map, bitmap, live counters
// ---------------------------------------------------------------------------
__global__ void __launch_bounds__(256) k_clear() {
    int t = blockIdx.x * blockDim.x + threadIdx.x;
    if (t < AGG4) {
        reinterpret_cast<float4*>(g_agg)[t] = make_float4(0.f, 0.f, 0.f, 0.f);
    } else {
        int u = t - AGG4;
        if (u < NU + NI) g_rowid[u] = -1;
        else {
            int b = u - (NU + NI);
            if (b < BMW) g_bitmap[b] = 0u;
            else if (b == BMW) { g_nlive_u = 0; g_nlive_i = 0; }
        }
    }
}

// ---------------------------------------------------------------------------
// K1: flag rows: set bitmap bit + CAS-claim compact id (side-partitioned:
//     users get ids [0,8192), items ids [8192,24576))
// ---------------------------------------------------------------------------
__global__ void __launch_bounds__(256) k_flags(const int* __restrict__ ui,
                                               const int* __restrict__ ii,
                                               const int* __restrict__ ni) {
    int t = blockIdx.x * blockDim.x + threadIdx.x;
    int rg; bool user;
    if (t < BATCH)          { rg = ui[t];                user = true;  }
    else if (t < 2 * BATCH) { rg = NU + ii[t - BATCH];   user = false; }
    else if (t < 3 * BATCH) { rg = NU + ni[t - 2*BATCH]; user = false; }
    else return;

    atomicOr(&g_bitmap[rg >> 5], 1u << (rg & 31));
    if (atomicCAS(&g_rowid[rg], -1, -2) == -1) {
        int id = user ? atomicAdd(&g_nlive_u, 1)
                      : (UIDS + atomicAdd(&g_nlive_i, 1));
        g_rowid[rg] = id;
    }
}

// ---------------------------------------------------------------------------
// K2: fused filter + scatter (proven round-10 shape).  SMEM bitmap filter,
//     ballot/half-warp cooperative red.v4 scatter into L2-resident agg.
// ---------------------------------------------------------------------------
__global__ void __launch_bounds__(256) k_scatter(const int*   __restrict__ u_rows,
                                                 const int*   __restrict__ u_cols,
                                                 const float* __restrict__ u_vals,
                                                 const int*   __restrict__ i_rows,
                                                 const int*   __restrict__ i_cols,
                                                 const float* __restrict__ i_vals,
                                                 const float* __restrict__ u_table,
                                                 const float* __restrict__ i_table) {
    __shared__ unsigned sbm[BMW];                // 18752 B
    for (int i = threadIdx.x; i < BMW; i += blockDim.x) sbm[i] = g_bitmap[i];
    __syncthreads();

    const int lane = threadIdx.x & 31;
    const int sub  = lane & 15;
    const int half = lane >> 4;
    constexpr int NGRP = NP * (EU + EI) / 32;    // 225000 groups of 32 edges
    int gw = (blockIdx.x * blockDim.x + threadIdx.x) >> 5;
    int wstride = (gridDim.x * blockDim.x) >> 5;

    for (int grp = gw; grp < NGRP; grp += wstride) {
        int e0 = grp * 32;
        const int* rows; const int* cols; const float* vals; const float* table;
        int e, p, roff;
        if (e0 < NP * EU) {
            e = e0;            p = e / EU;
            rows = u_rows; cols = u_cols; vals = u_vals; table = u_table; roff = 0;
        } else {
            e = e0 - NP * EU;  p = e / EI;
            rows = i_rows; cols = i_cols; vals = i_vals; table = i_table; roff = NU;
        }

        int r = __ldg(rows + e + lane);
        int x = roff + r;
        bool ok = (sbm[x >> 5] >> (x & 31)) & 1u;
        int slot = 0, c = 0; float v = 0.f;
        if (ok) {
            slot = g_rowid[x] * NP + p;
            c = __ldg(cols + e + lane);
            v = __ldg(vals + e + lane);
        }

        unsigned m = __ballot_sync(0xffffffffu, ok);
        while (m) {
            int srcA = __ffs(m) - 1; m &= m - 1;
            int srcB = m ? (__ffs(m) - 1) : -1;
            if (srcB >= 0) m &= m - 1;
            int src = half ? srcB : srcA;
            bool act = (src >= 0);
            int sx = act ? src : 0;
            int   sl = __shfl_sync(0xffffffffu, slot, sx);
            int   cc = __shfl_sync(0xffffffffu, c,    sx);
            float vv = __shfl_sync(0xffffffffu, v,    sx);
            if (act) {
                float4 s = __ldg(reinterpret_cast<const float4*>(table + (size_t)cc * D) + sub);
                float* dst = g_agg + (size_t)sl * D + (size_t)sub * 4;
                asm volatile("red.global.add.v4.f32 [%0], {%1, %2, %3, %4};"
                             :: "l"(dst), "f"(s.x * vv), "f"(s.y * vv),
                                "f"(s.z * vv), "f"(s.w * vv)
                             : "memory");
            }
        }
    }
}

// ---------------------------------------------------------------------------
// K3: dense per-path GEMM over the compact id space (NO gather!).
//     Block = (64 consecutive ids, one path).  A rows contiguous in g_agg.
//     35 KB static smem; one staging phase + one sync; 4x4 register tile.
//     m[id,p] = agg[id,p] @ W_{side(id),p}  ->  g_m
// ---------------------------------------------------------------------------
static constexpr int TROWS = 64;
static constexpr int SPAD  = 68;                 // padded k-row stride (16B-aligned)

__global__ void __launch_bounds__(256) k_gemm(const float* __restrict__ Wu,
                                              const float* __restrict__ Wi) {
    __shared__ float As[D * SPAD];               // As[k*SPAD + r], 17.4 KB
    __shared__ float Ws[D * SPAD];               // Ws[k*SPAD + c], 17.4 KB

    int rb = blockIdx.x / NP;                    // id block
    int p  = blockIdx.x % NP;
    int id0 = rb * TROWS;
    bool user = (id0 < UIDS);                    // UIDS % TROWS == 0 -> uniform side
    int livecnt = user ? g_nlive_u : g_nlive_i;
    if ((user ? id0 : (id0 - UIDS)) >= livecnt) return;   // wholly-dead id block

    const float* W = (user ? Wu : Wi) + p * D * D;
    int tid = threadIdx.x;

    // Stage W_p (coalesced) and A transposed (contiguous ids, coalesced 256B rows)
    #pragma unroll
    for (int j = tid; j < D * D; j += 256) {
        int k = j >> 6, c = j & 63;
        Ws[k * SPAD + c] = __ldg(W + j);
    }
    #pragma unroll
    for (int j = tid; j < TROWS * D; j += 256) {
        int r = j >> 6, k = j & 63;
        As[k * SPAD + r] = g_agg[(size_t)((id0 + r) * NP + p) * D + k];
    }
    __syncthreads();

    int tx = tid & 15, ty = tid >> 4;
    int c0 = tx * 4, r0 = ty * 4;

    float m[4][4];
    #pragma unroll
    for (int i = 0; i < 4; i++)
        #pragma unroll
        for (int j = 0; j < 4; j++) m[i][j] = 0.f;

    #pragma unroll
    for (int k = 0; k < D; k++) {
        float4 a = *reinterpret_cast<const float4*>(&As[k * SPAD + r0]);
        float4 b = *reinterpret_cast<const float4*>(&Ws[k * SPAD + c0]);
        float av[4] = {a.x, a.y, a.z, a.w};
        float bv[4] = {b.x, b.y, b.z, b.w};
        #pragma unroll
        for (int i = 0; i < 4; i++)
            #pragma unroll
            for (int j = 0; j < 4; j++)
                m[i][j] += av[i] * bv[j];
    }

    #pragma unroll
    for (int i = 0; i < 4; i++) {
        float4 o4 = make_float4(m[i][0], m[i][1], m[i][2], m[i][3]);
        *reinterpret_cast<float4*>(
            &g_m[(size_t)((id0 + r0 + i) * NP + p) * D + c0]) = o4;
    }
}

// ---------------------------------------------------------------------------
// K4: combine.  out[seg][b] = relu( sum_p wb[p] * relu( g_m[id(b), p] ) )
//     16 threads per output row (float4 each); pure elementwise, L2-resident.
// ---------------------------------------------------------------------------
__global__ void __launch_bounds__(256) k_comb(const float* __restrict__ wb1,
                                              const float* __restrict__ wb2,
                                              const int*   __restrict__ ui,
                                              const int*   __restrict__ ii,
                                              const int*   __restrict__ ni,
                                              float*       __restrict__ out) {
    int t = blockIdx.x * blockDim.x + threadIdx.x;
    int row = t >> 4, q = t & 15;
    if (row >= 3 * BATCH) return;
    int seg = row / BATCH, b = row % BATCH;

    const int*   idxA = (seg == 0) ? ui : ((seg == 1) ? ii : ni);
    const float* wbp  = (seg == 0) ? wb1 : wb2;
    int roff = (seg == 0) ? 0 : NU;

    int id = g_rowid[roff + __ldg(idxA + b)];
    float w0 = __ldg(wbp + 0), w1 = __ldg(wbp + 1), w2 = __ldg(wbp + 2);

    const float* mb = g_m + (size_t)id * NP * D + q * 4;
    float4 m0 = *reinterpret_cast<const float4*>(mb);
    float4 m1 = *reinterpret_cast<const float4*>(mb + D);
    float4 m2 = *reinterpret_cast<const float4*>(mb + 2 * D);

    float4 o;
    o.x = fmaxf(w0 * fmaxf(m0.x, 0.f) + w1 * fmaxf(m1.x, 0.f) + w2 * fmaxf(m2.x, 0.f), 0.f);
    o.y = fmaxf(w0 * fmaxf(m0.y, 0.f) + w1 * fmaxf(m1.y, 0.f) + w2 * fmaxf(m2.y, 0.f), 0.f);
    o.z = fmaxf(w0 * fmaxf(m0.z, 0.f) + w1 * fmaxf(m1.z, 0.f) + w2 * fmaxf(m2.z, 0.f), 0.f);
    o.w = fmaxf(w0 * fmaxf(m0.w, 0.f) + w1 * fmaxf(m1.w, 0.f) + w2 * fmaxf(m2.w, 0.f), 0.f);

    *reinterpret_cast<float4*>(out + ((size_t)seg * BATCH + b) * D + q * 4) = o;
}

// ---------------------------------------------------------------------------
// Launch
// ---------------------------------------------------------------------------
extern "C" void kernel_launch(void* const* d_in, const int* in_sizes, int n_in,
                              void* d_out, int out_size) {
    const float* user_table = (const float*)d_in[0];
    const float* item_table = (const float*)d_in[1];
    const float* Wu         = (const float*)d_in[2];
    const float* Wi         = (const float*)d_in[3];
    const float* wb1        = (const float*)d_in[4];
    const float* wb2        = (const float*)d_in[5];
    const float* user_vals  = (const float*)d_in[6];
    const float* item_vals  = (const float*)d_in[7];
    const int*   user_rows  = (const int*)d_in[8];
    const int*   user_cols  = (const int*)d_in[9];
    const int*   item_rows  = (const int*)d_in[10];
    const int*   item_cols  = (const int*)d_in[11];
    const int*   user_idx   = (const int*)d_in[12];
    const int*   item_idx   = (const int*)d_in[13];
    const int*   neg_idx    = (const int*)d_in[14];
    float* out = (float*)d_out;

    k_clear<<<cdiv(AGG4 + NU + NI + BMW + 1, 256), 256>>>();
    k_flags<<<cdiv(3 * BATCH, 256), 256>>>(user_idx, item_idx, neg_idx);
    k_scatter<<<1184, 256>>>(user_rows, user_cols, user_vals,
                             item_rows, item_cols, item_vals,
                             user_table, item_table);
    k_gemm<<<(MAXROWS / TROWS) * NP, 256>>>(Wu, Wi);
    k_comb<<<cdiv(3 * BATCH * 16, 256), 256>>>(wb1, wb2, user_idx, item_idx, neg_idx, out);
}

// round 13
// speedup vs baseline: 1.7087x; 1.0960x over previous
#include <cuda_runtime.h>
#include <cstdint>

// Problem constants (fixed by the reference).
static constexpr int NU    = 100000;   // users
static constexpr int NI    = 50000;    // items
static constexpr int D     = 64;       // dim
static constexpr int NP    = 3;        // meta-paths
static constexpr int DEG   = 16;
static constexpr int EU    = NU * DEG; // edges per user path (1.6M)
static constexpr int EI    = NI * DEG; // edges per item path (0.8M)
static constexpr int BATCH = 8192;

static constexpr int UIDS     = BATCH;                // user id region [0, 8192)
static constexpr int MAXROWS  = 3 * BATCH;            // 24576 ids (items at [8192, 24576))
static constexpr int MAXSLOTS = MAXROWS * NP;         // 73728 (id, path) slots
static constexpr int CAP      = 64;                   // max edges per slot bin
static constexpr int BMW      = (NU + NI + 31) / 32;  // 4688 bitmap words (18.75 KB)

// Scratch (static device memory; ~57 MB total).
__device__ float              g_agg[(size_t)MAXSLOTS * D];    // 18.9 MB (written fully by process)
__device__ float              g_m[(size_t)MAXSLOTS * D];      // 18.9 MB per-path GEMM result
__device__ unsigned long long g_bin[(size_t)MAXSLOTS * CAP];  // 37.7 MB
__device__ int                g_cnt[MAXSLOTS];                // 295 KB
__device__ int                g_rowid[NU + NI];               // 600 KB (-1 = not live)
__device__ unsigned           g_bitmap[BMW];                  // 18.75 KB
__device__ int                g_nlive_u;
__device__ int                g_nlive_i;

static inline unsigned cdiv(long long a, long long b) { return (unsigned)((a + b - 1) / b); }

// ---------------------------------------------------------------------------
// K0: clear rowid map, bitmap, bin cursors, live counters (no agg zero!)
// ---------------------------------------------------------------------------
__global__ void __launch_bounds__(256) k_clear() {
    int t = blockIdx.x * blockDim.x + threadIdx.x;
    if (t < NU + NI) g_rowid[t] = -1;
    int b = t - (NU + NI);
    if (b >= 0 && b < BMW) g_bitmap[b] = 0u;
    int c = t - (NU + NI + BMW);
    if (c >= 0 && c < MAXSLOTS) g_cnt[c] = 0;
    if (t == 0) { g_nlive_u = 0; g_nlive_i = 0; }
}

// ---------------------------------------------------------------------------
// K1: flag rows: bitmap bit + CAS-claim side-partitioned compact id
// ---------------------------------------------------------------------------
__global__ void __launch_bounds__(256) k_flags(const int* __restrict__ ui,
                                               const int* __restrict__ ii,
                                               const int* __restrict__ ni) {
    int t = blockIdx.x * blockDim.x + threadIdx.x;
    int rg; bool user;
    if (t < BATCH)          { rg = ui[t];                user = true;  }
    else if (t < 2 * BATCH) { rg = NU + ii[t - BATCH];   user = false; }
    else if (t < 3 * BATCH) { rg = NU + ni[t - 2*BATCH]; user = false; }
    else return;

    atomicOr(&g_bitmap[rg >> 5], 1u << (rg & 31));
    if (atomicCAS(&g_rowid[rg], -1, -2) == -1) {
        int id = user ? atomicAdd(&g_nlive_u, 1)
                      : (UIDS + atomicAdd(&g_nlive_i, 1));
        g_rowid[rg] = id;
    }
}

// ---------------------------------------------------------------------------
// K2: bin pass (round-8 proven shape).  SMEM bitmap filter; 4 edges/thread
//     via int4 metadata loads; survivors drop packed (val,col) into bins.
// ---------------------------------------------------------------------------
__global__ void __launch_bounds__(256) k_bin(const int*   __restrict__ u_rows,
                                             const int*   __restrict__ u_cols,
                                             const float* __restrict__ u_vals,
                                             const int*   __restrict__ i_rows,
                                             const int*   __restrict__ i_cols,
                                             const float* __restrict__ i_vals) {
    __shared__ unsigned sbm[BMW];                // 18752 B
    for (int i = threadIdx.x; i < BMW; i += blockDim.x) sbm[i] = g_bitmap[i];
    __syncthreads();

    constexpr long long NG = (long long)NP * (EU + EI) / 4;   // 1.8M groups of 4
    const long long stride = (long long)gridDim.x * blockDim.x;

    for (long long g = (long long)blockIdx.x * blockDim.x + threadIdx.x;
         g < NG; g += stride) {
        long long e0 = g * 4;
        const int* rows; const int* cols; const float* vals;
        int e, p, roff;
        if (e0 < (long long)NP * EU) {
            e = (int)e0;  p = e / EU;
            rows = u_rows; cols = u_cols; vals = u_vals; roff = 0;
        } else {
            e = (int)(e0 - (long long)NP * EU);  p = e / EI;
            rows = i_rows; cols = i_cols; vals = i_vals; roff = NU;
        }

        int4 r4 = __ldg(reinterpret_cast<const int4*>(rows + e));
        int x0 = roff + r4.x, x1 = roff + r4.y, x2 = roff + r4.z, x3 = roff + r4.w;
        unsigned b0 = (sbm[x0 >> 5] >> (x0 & 31)) & 1u;
        unsigned b1 = (sbm[x1 >> 5] >> (x1 & 31)) & 1u;
        unsigned b2 = (sbm[x2 >> 5] >> (x2 & 31)) & 1u;
        unsigned b3 = (sbm[x3 >> 5] >> (x3 & 31)) & 1u;
        if (!(b0 | b1 | b2 | b3)) continue;

        int4   c4 = __ldg(reinterpret_cast<const int4*>(cols + e));
        float4 v4 = __ldg(reinterpret_cast<const float4*>(vals + e));

        if (b0) {
            int slot = g_rowid[x0] * NP + p;
            int pos = atomicAdd(&g_cnt[slot], 1);
            if (pos < CAP)
                g_bin[(size_t)slot * CAP + pos] =
                    ((unsigned long long)__float_as_uint(v4.x) << 32) | (unsigned)c4.x;
        }
        if (b1) {
            int slot = g_rowid[x1] * NP + p;
            int pos = atomicAdd(&g_cnt[slot], 1);
            if (pos < CAP)
                g_bin[(size_t)slot * CAP + pos] =
                    ((unsigned long long)__float_as_uint(v4.y) << 32) | (unsigned)c4.y;
        }
        if (b2) {
            int slot = g_rowid[x2] * NP + p;
            int pos = atomicAdd(&g_cnt[slot], 1);
            if (pos < CAP)
                g_bin[(size_t)slot * CAP + pos] =
                    ((unsigned long long)__float_as_uint(v4.z) << 32) | (unsigned)c4.z;
        }
        if (b3) {
            int slot = g_rowid[x3] * NP + p;
            int pos = atomicAdd(&g_cnt[slot], 1);
            if (pos < CAP)
                g_bin[(size_t)slot * CAP + pos] =
                    ((unsigned long long)__float_as_uint(v4.w) << 32) | (unsigned)c4.w;
        }
    }
}

// ---------------------------------------------------------------------------
// K3: per-slot reduction.  One warp per live (id,path) slot.  Per 32-entry
//     chunk: ONE coalesced bin load across lanes, then shuffle-broadcast each
//     (col,val); inner step = 2xSHFL + LDG.64 gather + 2xFFMA (unroll 4).
//     Register accumulation; single 256B store; no atomics, no zeroing.
// ---------------------------------------------------------------------------
__global__ void __launch_bounds__(128) k_process(const float* __restrict__ u_table,
                                                 const float* __restrict__ i_table) {
    int slot = blockIdx.x * (blockDim.x >> 5) + (threadIdx.x >> 5);
    if (slot >= MAXSLOTS) return;
    int id = slot / NP;
    bool user = id < UIDS;
    int live = user ? g_nlive_u : g_nlive_i;
    if ((user ? id : (id - UIDS)) >= live) return;

    int lane = threadIdx.x & 31;
    const float* table = user ? u_table : i_table;
    int n = min(g_cnt[slot], CAP);
    const unsigned long long* bin = g_bin + (size_t)slot * CAP;

    float2 acc = {0.f, 0.f};
    for (int base = 0; base < n; base += 32) {
        int m = min(32, n - base);
        unsigned long long pk = (lane < m) ? __ldg(bin + base + lane) : 0ull;
        unsigned lo = (unsigned)pk;
        unsigned hi = (unsigned)(pk >> 32);
        #pragma unroll 4
        for (int k = 0; k < m; k++) {
            unsigned c = __shfl_sync(0xffffffffu, lo, k);
            float    v = __uint_as_float(__shfl_sync(0xffffffffu, hi, k));
            float2 t = __ldg(reinterpret_cast<const float2*>(table + (size_t)c * D) + lane);
            acc.x += v * t.x;
            acc.y += v * t.y;
        }
    }
    reinterpret_cast<float2*>(g_agg + (size_t)slot * D)[lane] = acc;
}

// ---------------------------------------------------------------------------
// K4: dense per-path GEMM over the compact id space (proven round-12 shape).
// ---------------------------------------------------------------------------
static constexpr int TROWS = 64;
static constexpr int SPAD  = 68;

__global__ void __launch_bounds__(256) k_gemm(const float* __restrict__ Wu,
                                              const float* __restrict__ Wi) {
    __shared__ float As[D * SPAD];
    __shared__ float Ws[D * SPAD];

    int rb = blockIdx.x / NP;
    int p  = blockIdx.x % NP;
    int id0 = rb * TROWS;
    bool user = (id0 < UIDS);
    int livecnt = user ? g_nlive_u : g_nlive_i;
    if ((user ? id0 : (id0 - UIDS)) >= livecnt) return;

    const float* W = (user ? Wu : Wi) + p * D * D;
    int tid = threadIdx.x;

    #pragma unroll
    for (int j = tid; j < D * D; j += 256) {
        int k = j >> 6, c = j & 63;
        Ws[k * SPAD + c] = __ldg(W + j);
    }
    #pragma unroll
    for (int j = tid; j < TROWS * D; j += 256) {
        int r = j >> 6, k = j & 63;
        As[k * SPAD + r] = g_agg[(size_t)((id0 + r) * NP + p) * D + k];
    }
    __syncthreads();

    int tx = tid & 15, ty = tid >> 4;
    int c0 = tx * 4, r0 = ty * 4;

    float m[4][4];
    #pragma unroll
    for (int i = 0; i < 4; i++)
        #pragma unroll
        for (int j = 0; j < 4; j++) m[i][j] = 0.f;

    #pragma unroll
    for (int k = 0; k < D; k++) {
        float4 a = *reinterpret_cast<const float4*>(&As[k * SPAD + r0]);
        float4 b = *reinterpret_cast<const float4*>(&Ws[k * SPAD + c0]);
        float av[4] = {a.x, a.y, a.z, a.w};
        float bv[4] = {b.x, b.y, b.z, b.w};
        #pragma unroll
        for (int i = 0; i < 4; i++)
            #pragma unroll
            for (int j = 0; j < 4; j++)
                m[i][j] += av[i] * bv[j];
    }

    #pragma unroll
    for (int i = 0; i < 4; i++) {
        float4 o4 = make_float4(m[i][0], m[i][1], m[i][2], m[i][3]);
        *reinterpret_cast<float4*>(
            &g_m[(size_t)((id0 + r0 + i) * NP + p) * D + c0]) = o4;
    }
}

// ---------------------------------------------------------------------------
// K5: combine (proven round-12 shape).
// ---------------------------------------------------------------------------
__global__ void __launch_bounds__(256) k_comb(const float* __restrict__ wb1,
                                              const float* __restrict__ wb2,
                                              const int*   __restrict__ ui,
                                              const int*   __restrict__ ii,
                                              const int*   __restrict__ ni,
                                              float*       __restrict__ out) {
    int t = blockIdx.x * blockDim.x + threadIdx.x;
    int row = t >> 4, q = t & 15;
    if (row >= 3 * BATCH) return;
    int seg = row / BATCH, b = row % BATCH;

    const int*   idxA = (seg == 0) ? ui : ((seg == 1) ? ii : ni);
    const float* wbp  = (seg == 0) ? wb1 : wb2;
    int roff = (seg == 0) ? 0 : NU;

    int id = g_rowid[roff + __ldg(idxA + b)];
    float w0 = __ldg(wbp + 0), w1 = __ldg(wbp + 1), w2 = __ldg(wbp + 2);

    const float* mb = g_m + (size_t)id * NP * D + q * 4;
    float4 m0 = *reinterpret_cast<const float4*>(mb);
    float4 m1 = *reinterpret_cast<const float4*>(mb + D);
    float4 m2 = *reinterpret_cast<const float4*>(mb + 2 * D);

    float4 o;
    o.x = fmaxf(w0 * fmaxf(m0.x, 0.f) + w1 * fmaxf(m1.x, 0.f) + w2 * fmaxf(m2.x, 0.f), 0.f);
    o.y = fmaxf(w0 * fmaxf(m0.y, 0.f) + w1 * fmaxf(m1.y, 0.f) + w2 * fmaxf(m2.y, 0.f), 0.f);
    o.z = fmaxf(w0 * fmaxf(m0.z, 0.f) + w1 * fmaxf(m1.z, 0.f) + w2 * fmaxf(m2.z, 0.f), 0.f);
    o.w = fmaxf(w0 * fmaxf(m0.w, 0.f) + w1 * fmaxf(m1.w, 0.f) + w2 * fmaxf(m2.w, 0.f), 0.f);

    *reinterpret_cast<float4*>(out + ((size_t)seg * BATCH + b) * D + q * 4) = o;
}

// ---------------------------------------------------------------------------
// Launch
// ---------------------------------------------------------------------------
extern "C" void kernel_launch(void* const* d_in, const int* in_sizes, int n_in,
                              void* d_out, int out_size) {
    const float* user_table = (const float*)d_in[0];
    const float* item_table = (const float*)d_in[1];
    const float* Wu         = (const float*)d_in[2];
    const float* Wi         = (const float*)d_in[3];
    const float* wb1        = (const float*)d_in[4];
    const float* wb2        = (const float*)d_in[5];
    const float* user_vals  = (const float*)d_in[6];
    const float* item_vals  = (const float*)d_in[7];
    const int*   user_rows  = (const int*)d_in[8];
    const int*   user_cols  = (const int*)d_in[9];
    const int*   item_rows  = (const int*)d_in[10];
    const int*   item_cols  = (const int*)d_in[11];
    const int*   user_idx   = (const int*)d_in[12];
    const int*   item_idx   = (const int*)d_in[13];
    const int*   neg_idx    = (const int*)d_in[14];
    float* out = (float*)d_out;

    k_clear<<<cdiv(NU + NI + BMW + MAXSLOTS, 256), 256>>>();
    k_flags<<<cdiv(3 * BATCH, 256), 256>>>(user_idx, item_idx, neg_idx);
    k_bin<<<1184, 256>>>(user_rows, user_cols, user_vals,
                         item_rows, item_cols, item_vals);
    k_process<<<cdiv(MAXSLOTS, 4), 128>>>(user_table, item_table);
    k_gemm<<<(MAXROWS / TROWS) * NP, 256>>>(Wu, Wi);
    k_comb<<<cdiv(3 * BATCH * 16, 256), 256>>>(wb1, wb2, user_idx, item_idx, neg_idx, out);
}